// round 6
// baseline (speedup 1.0000x reference)
#include <cuda_runtime.h>

#define D_FEAT    128
#define N_CLASS   10
#define PSTRIDE   12
#define MAX_NODES 100000

__device__ __align__(16) float g_P[MAX_NODES * PSTRIDE];
__device__ __align__(16) float g_Q[MAX_NODES * PSTRIDE];

// packed f32x2 fma: acc += a * b (two fp32 lanes per instruction)
#define FFMA2(acc, a, b) \
    asm("fma.rn.f32x2 %0, %1, %2, %0;" : "+l"(acc) : "l"(a), "l"(b))

__device__ __forceinline__ float unpack_sum(unsigned long long p) {
    return __uint_as_float((unsigned)(p & 0xffffffffu)) +
           __uint_as_float((unsigned)(p >> 32));
}

// ---------------------------------------------------------------------------
// Kernel 1: node projection. Warp-cooperative: 8 lanes/node, 4 nodes/warp.
//   P[n] = h[n] @ W[:,0:128]^T + b ;  Q[n] = h[n] @ W[:,128:256]^T
// ---------------------------------------------------------------------------
__global__ void node_project_kernel(const float* __restrict__ h,
                                    const float* __restrict__ W,
                                    const float* __restrict__ b,
                                    int n_nodes) {
    __shared__ __align__(16) float sWU[N_CLASS * 128];
    __shared__ __align__(16) float sWV[N_CLASS * 128];
    __shared__ float bsh[N_CLASS];

    int tid = threadIdx.x;
    for (int i = tid; i < N_CLASS * 128; i += blockDim.x) {
        int c = i >> 7, j = i & 127;
        sWU[i] = W[c * 384 + j];
        sWV[i] = W[c * 384 + 128 + j];
    }
    if (tid < N_CLASS) bsh[tid] = b[tid];
    __syncthreads();

    int lane = tid & 31;
    int gwarp = (blockIdx.x * blockDim.x + tid) >> 5;
    int g = lane >> 3, j = lane & 7;
    int n = gwarp * 4 + g;
    int nn = n < n_nodes ? n : (n_nodes - 1);

    const float4* row = (const float4*)(h + (size_t)nn * D_FEAT);
    float4 v0 = row[j], v1 = row[j + 8], v2 = row[j + 16], v3 = row[j + 24];
    ulonglong2 u0 = *(const ulonglong2*)&v0;
    ulonglong2 u1 = *(const ulonglong2*)&v1;
    ulonglong2 u2 = *(const ulonglong2*)&v2;
    ulonglong2 u3 = *(const ulonglong2*)&v3;

    const ulonglong2* WU = (const ulonglong2*)sWU;  // [c*32 + k*8 + j]
    const ulonglong2* WV = (const ulonglong2*)sWV;

    unsigned long long accU[N_CLASS], accV[N_CLASS];
#pragma unroll
    for (int c = 0; c < N_CLASS; c++) { accU[c] = 0ull; accV[c] = 0ull; }

#pragma unroll
    for (int c = 0; c < N_CLASS; c++) {
        ulonglong2 a0 = WU[c * 32 + j];
        ulonglong2 a1 = WU[c * 32 + 8 + j];
        ulonglong2 a2 = WU[c * 32 + 16 + j];
        ulonglong2 a3 = WU[c * 32 + 24 + j];
        FFMA2(accU[c], u0.x, a0.x); FFMA2(accU[c], u0.y, a0.y);
        FFMA2(accU[c], u1.x, a1.x); FFMA2(accU[c], u1.y, a1.y);
        FFMA2(accU[c], u2.x, a2.x); FFMA2(accU[c], u2.y, a2.y);
        FFMA2(accU[c], u3.x, a3.x); FFMA2(accU[c], u3.y, a3.y);
        ulonglong2 b0 = WV[c * 32 + j];
        ulonglong2 b1 = WV[c * 32 + 8 + j];
        ulonglong2 b2 = WV[c * 32 + 16 + j];
        ulonglong2 b3 = WV[c * 32 + 24 + j];
        FFMA2(accV[c], u0.x, b0.x); FFMA2(accV[c], u0.y, b0.y);
        FFMA2(accV[c], u1.x, b1.x); FFMA2(accV[c], u1.y, b1.y);
        FFMA2(accV[c], u2.x, b2.x); FFMA2(accV[c], u2.y, b2.y);
        FFMA2(accV[c], u3.x, b3.x); FFMA2(accV[c], u3.y, b3.y);
    }

    float rU[N_CLASS], rV[N_CLASS];
#pragma unroll
    for (int c = 0; c < N_CLASS; c++) {
        rU[c] = unpack_sum(accU[c]);
        rV[c] = unpack_sum(accV[c]);
    }
#pragma unroll
    for (int off = 4; off >= 1; off >>= 1) {
#pragma unroll
        for (int c = 0; c < N_CLASS; c++) {
            rU[c] += __shfl_down_sync(0xffffffffu, rU[c], off, 8);
            rV[c] += __shfl_down_sync(0xffffffffu, rV[c], off, 8);
        }
    }

    if (j == 0 && n < n_nodes) {
        float4* Pr = (float4*)(g_P + (size_t)n * PSTRIDE);
        float4* Qr = (float4*)(g_Q + (size_t)n * PSTRIDE);
        Pr[0] = make_float4(rU[0] + bsh[0], rU[1] + bsh[1], rU[2] + bsh[2], rU[3] + bsh[3]);
        Pr[1] = make_float4(rU[4] + bsh[4], rU[5] + bsh[5], rU[6] + bsh[6], rU[7] + bsh[7]);
        Pr[2] = make_float4(rU[8] + bsh[8], rU[9] + bsh[9], 0.f, 0.f);
        Qr[0] = make_float4(rV[0], rV[1], rV[2], rV[3]);
        Qr[1] = make_float4(rV[4], rV[5], rV[6], rV[7]);
        Qr[2] = make_float4(rV[8], rV[9], 0.f, 0.f);
    }
}

// ---------------------------------------------------------------------------
// Kernel 2: per-edge. Warp-cooperative: 8 lanes/edge, 4 edges/warp.
//   out[e] = edge_h[e] @ W[:,256:384]^T + P[src[e]] + Q[dst[e]]
// Each LDG.128 warp instruction covers 4 full 128B lines (coalesced).
// ---------------------------------------------------------------------------
__global__ void edge_score_kernel(const float* __restrict__ eh,
                                  const float* __restrict__ W,
                                  const int* __restrict__ src,
                                  const int* __restrict__ dst,
                                  float* __restrict__ out,
                                  int n_edges) {
    __shared__ __align__(16) float sW[N_CLASS * 128];
    int tid = threadIdx.x;
    for (int i = tid; i < N_CLASS * 128; i += blockDim.x) {
        int c = i >> 7, j = i & 127;
        sW[i] = W[c * 384 + 256 + j];
    }
    __syncthreads();

    int lane = tid & 31;
    int gwarp = (blockIdx.x * blockDim.x + tid) >> 5;
    int g = lane >> 3, j = lane & 7;
    int e = gwarp * 4 + g;
    int ee = e < n_edges ? e : (n_edges - 1);

    const float4* row = (const float4*)(eh + (size_t)ee * D_FEAT);
    float4 v0 = row[j], v1 = row[j + 8], v2 = row[j + 16], v3 = row[j + 24];
    ulonglong2 u0 = *(const ulonglong2*)&v0;
    ulonglong2 u1 = *(const ulonglong2*)&v1;
    ulonglong2 u2 = *(const ulonglong2*)&v2;
    ulonglong2 u3 = *(const ulonglong2*)&v3;

    const ulonglong2* Wp = (const ulonglong2*)sW;   // [c*32 + k*8 + j]

    unsigned long long acc[N_CLASS];
#pragma unroll
    for (int c = 0; c < N_CLASS; c++) acc[c] = 0ull;

#pragma unroll
    for (int c = 0; c < N_CLASS; c++) {
        ulonglong2 w0 = Wp[c * 32 + j];
        ulonglong2 w1 = Wp[c * 32 + 8 + j];
        ulonglong2 w2 = Wp[c * 32 + 16 + j];
        ulonglong2 w3 = Wp[c * 32 + 24 + j];
        FFMA2(acc[c], u0.x, w0.x); FFMA2(acc[c], u0.y, w0.y);
        FFMA2(acc[c], u1.x, w1.x); FFMA2(acc[c], u1.y, w1.y);
        FFMA2(acc[c], u2.x, w2.x); FFMA2(acc[c], u2.y, w2.y);
        FFMA2(acc[c], u3.x, w3.x); FFMA2(acc[c], u3.y, w3.y);
    }

    float r[N_CLASS];
#pragma unroll
    for (int c = 0; c < N_CLASS; c++) r[c] = unpack_sum(acc[c]);
#pragma unroll
    for (int off = 4; off >= 1; off >>= 1) {
#pragma unroll
        for (int c = 0; c < N_CLASS; c++)
            r[c] += __shfl_down_sync(0xffffffffu, r[c], off, 8);
    }

    if (j == 0 && e < n_edges) {
        int s = src[e];
        int d = dst[e];
        const float4* Pr = (const float4*)(g_P + (size_t)s * PSTRIDE);
        const float4* Qr = (const float4*)(g_Q + (size_t)d * PSTRIDE);
        float4 p0 = Pr[0], p1 = Pr[1], p2 = Pr[2];
        float4 q0 = Qr[0], q1 = Qr[1], q2 = Qr[2];

        float2* o2 = (float2*)(out + (size_t)e * N_CLASS);
        o2[0] = make_float2(r[0] + p0.x + q0.x, r[1] + p0.y + q0.y);
        o2[1] = make_float2(r[2] + p0.z + q0.z, r[3] + p0.w + q0.w);
        o2[2] = make_float2(r[4] + p1.x + q1.x, r[5] + p1.y + q1.y);
        o2[3] = make_float2(r[6] + p1.z + q1.z, r[7] + p1.w + q1.w);
        o2[4] = make_float2(r[8] + p2.x + q2.x, r[9] + p2.y + q2.y);
    }
}

// ---------------------------------------------------------------------------
extern "C" void kernel_launch(void* const* d_in, const int* in_sizes, int n_in,
                              void* d_out, int out_size) {
    const float* h   = (const float*)d_in[0];
    const float* eh  = (const float*)d_in[1];
    const float* W   = (const float*)d_in[2];
    const float* b   = (const float*)d_in[3];
    const int*   src = (const int*)d_in[4];
    const int*   dst = (const int*)d_in[5];
    float*       out = (float*)d_out;

    int n_nodes = in_sizes[0] / D_FEAT;
    int n_edges = in_sizes[4];

    // 32 rows per 256-thread block (4 per warp)
    node_project_kernel<<<(n_nodes + 31) / 32, 256>>>(h, W, b, n_nodes);
    edge_score_kernel<<<(n_edges + 31) / 32, 256>>>(eh, W, src, dst, out, n_edges);
}

// round 9
// speedup vs baseline: 1.9591x; 1.9591x over previous
#include <cuda_runtime.h>

#define N_CLASS   10
#define PSTRIDE   12
#define MAX_NODES 100000

__device__ __align__(16) float g_P[MAX_NODES * PSTRIDE];
__device__ __align__(16) float g_Q[MAX_NODES * PSTRIDE];

// packed fp32x2 fma: acc += a * b
#define FFMA2(acc, a, b) \
    asm("fma.rn.f32x2 %0, %1, %2, %0;" : "+l"(acc) : "l"(a), "l"(b))

__device__ __forceinline__ unsigned long long pack2(float x, float y) {
    unsigned long long r;
    asm("mov.b64 %0, {%1, %2};" : "=l"(r) : "f"(x), "f"(y));
    return r;
}
__device__ __forceinline__ float2 unpack2(unsigned long long p) {
    float2 f;
    asm("mov.b64 {%0, %1}, %2;" : "=f"(f.x), "=f"(f.y) : "l"(p));
    return f;
}

// lane-resident weights: wp[p][k] = (W[2p][col], W[2p+1][col]) for this lane's 4 cols
__device__ __forceinline__ void load_weights(const float* __restrict__ W, int wcol,
                                             int lane, unsigned long long wp[5][4]) {
#pragma unroll
    for (int p = 0; p < 5; p++) {
        float4 wa = ((const float4*)(W + (2 * p) * 384 + wcol))[lane];
        float4 wb = ((const float4*)(W + (2 * p + 1) * 384 + wcol))[lane];
        wp[p][0] = pack2(wa.x, wb.x);
        wp[p][1] = pack2(wa.y, wb.y);
        wp[p][2] = pack2(wa.z, wb.z);
        wp[p][3] = pack2(wa.w, wb.w);
    }
}

__device__ __forceinline__ void dot10(const unsigned long long wp[5][4], float4 v,
                                      unsigned long long acc[5]) {
    unsigned long long a0 = pack2(v.x, v.x);
    unsigned long long a1 = pack2(v.y, v.y);
    unsigned long long a2 = pack2(v.z, v.z);
    unsigned long long a3 = pack2(v.w, v.w);
#pragma unroll
    for (int p = 0; p < 5; p++) {
        FFMA2(acc[p], a0, wp[p][0]);
        FFMA2(acc[p], a1, wp[p][1]);
        FFMA2(acc[p], a2, wp[p][2]);
        FFMA2(acc[p], a3, wp[p][3]);
    }
}

// Reduce 4 rows x 10 classes across the warp. After this, every lane of
// octet o holds the full 10-class result of row perm[o], perm = {0,2,1,3}.
__device__ __forceinline__ void reduce4x10(unsigned long long acc[4][5],
                                           float u[N_CLASS], int lane) {
    float p[4][N_CLASS];
#pragma unroll
    for (int g = 0; g < 4; g++)
#pragma unroll
        for (int q = 0; q < 5; q++) {
            float2 f = unpack2(acc[g][q]);
            p[g][2 * q] = f.x;
            p[g][2 * q + 1] = f.y;
        }

    bool lo16 = (lane & 16) == 0;
    float t0[N_CLASS], t1[N_CLASS];
#pragma unroll
    for (int c = 0; c < N_CLASS; c++) {
        float b0 = lo16 ? p[0][c] : p[1][c];
        float s0 = lo16 ? p[1][c] : p[0][c];
        t0[c] = b0 + __shfl_xor_sync(0xffffffffu, s0, 16);
        float b1 = lo16 ? p[2][c] : p[3][c];
        float s1 = lo16 ? p[3][c] : p[2][c];
        t1[c] = b1 + __shfl_xor_sync(0xffffffffu, s1, 16);
    }
    bool lo8 = (lane & 8) == 0;
#pragma unroll
    for (int c = 0; c < N_CLASS; c++) {
        float bc = lo8 ? t0[c] : t1[c];
        float sc = lo8 ? t1[c] : t0[c];
        float v = bc + __shfl_xor_sync(0xffffffffu, sc, 8);
        v += __shfl_xor_sync(0xffffffffu, v, 4);
        v += __shfl_xor_sync(0xffffffffu, v, 2);
        v += __shfl_xor_sync(0xffffffffu, v, 1);
        u[c] = v;
    }
}

// ---------------------------------------------------------------------------
// Node projection: which==0: g_P = h @ W[:,0:128]^T + b
//                  which==1: g_Q = h @ W[:,128:256]^T
// Destination resolved in DEVICE code (a __device__ symbol cannot be passed
// from host; on GB300/ATS that silently writes host shadow memory).
// ---------------------------------------------------------------------------
__global__ __launch_bounds__(128)
void proj_kernel(const float* __restrict__ X, const float* __restrict__ W,
                 const float* __restrict__ bias, int which, int n_rows) {
    float* outbuf = which ? g_Q : g_P;
    int wcol = which ? 128 : 0;

    int lane = threadIdx.x & 31;
    int warp = (blockIdx.x * blockDim.x + threadIdx.x) >> 5;
    int nwarps = (gridDim.x * blockDim.x) >> 5;

    unsigned long long wp[5][4];
    load_weights(W, wcol, lane, wp);

    const float4* Xv = (const float4*)X;
    int nm1 = n_rows - 1;

    for (int base = warp * 4; base < n_rows; base += nwarps * 4) {
        int i1 = min(base + 1, nm1), i2 = min(base + 2, nm1), i3 = min(base + 3, nm1);
        float4 v0 = Xv[(size_t)base * 32 + lane];
        float4 v1 = Xv[(size_t)i1 * 32 + lane];
        float4 v2 = Xv[(size_t)i2 * 32 + lane];
        float4 v3 = Xv[(size_t)i3 * 32 + lane];

        unsigned long long acc[4][5];
#pragma unroll
        for (int g = 0; g < 4; g++)
#pragma unroll
            for (int q = 0; q < 5; q++) acc[g][q] = 0ull;

        dot10(wp, v0, acc[0]);
        dot10(wp, v1, acc[1]);
        dot10(wp, v2, acc[2]);
        dot10(wp, v3, acc[3]);

        float u[N_CLASS];
        reduce4x10(acc, u, lane);

        int o = lane >> 3;
        int ridx = base + (((o & 1) << 1) | (o >> 1));   // perm {0,2,1,3}
        if ((lane & 7) == 0 && ridx < n_rows) {
            if (which == 0) {
#pragma unroll
                for (int c = 0; c < N_CLASS; c++) u[c] += __ldg(bias + c);
            }
            float4* O = (float4*)(outbuf + (size_t)ridx * PSTRIDE);
            O[0] = make_float4(u[0], u[1], u[2], u[3]);
            O[1] = make_float4(u[4], u[5], u[6], u[7]);
            O[2] = make_float4(u[8], u[9], 0.f, 0.f);
        }
    }
}

// ---------------------------------------------------------------------------
// Edge kernel: out[e] = eh[e] @ W[:,256:384]^T + P[src[e]] + Q[dst[e]]
// Warp-per-edge-row, 4 edges per pass, weights in registers.
// ---------------------------------------------------------------------------
__global__ __launch_bounds__(128)
void edge_score_kernel(const float* __restrict__ eh, const float* __restrict__ W,
                       const int* __restrict__ src, const int* __restrict__ dst,
                       float* __restrict__ out, int n_edges) {
    int lane = threadIdx.x & 31;
    int warp = (blockIdx.x * blockDim.x + threadIdx.x) >> 5;
    int nwarps = (gridDim.x * blockDim.x) >> 5;

    unsigned long long wp[5][4];
    load_weights(W, 256, lane, wp);

    const float4* Ev = (const float4*)eh;
    int nm1 = n_edges - 1;

    for (int base = warp * 4; base < n_edges; base += nwarps * 4) {
        int i1 = min(base + 1, nm1), i2 = min(base + 2, nm1), i3 = min(base + 3, nm1);
        float4 v0 = Ev[(size_t)base * 32 + lane];
        float4 v1 = Ev[(size_t)i1 * 32 + lane];
        float4 v2 = Ev[(size_t)i2 * 32 + lane];
        float4 v3 = Ev[(size_t)i3 * 32 + lane];

        unsigned long long acc[4][5];
#pragma unroll
        for (int g = 0; g < 4; g++)
#pragma unroll
            for (int q = 0; q < 5; q++) acc[g][q] = 0ull;

        dot10(wp, v0, acc[0]);
        dot10(wp, v1, acc[1]);
        dot10(wp, v2, acc[2]);
        dot10(wp, v3, acc[3]);

        float u[N_CLASS];
        reduce4x10(acc, u, lane);

        int o = lane >> 3;
        int eidx = base + (((o & 1) << 1) | (o >> 1));   // perm {0,2,1,3}
        if ((lane & 7) == 0 && eidx < n_edges) {
            int s = src[eidx];
            int d = dst[eidx];
            const float4* Pr = (const float4*)(g_P + (size_t)s * PSTRIDE);
            const float4* Qr = (const float4*)(g_Q + (size_t)d * PSTRIDE);
            float4 p0 = Pr[0], p1 = Pr[1], p2 = Pr[2];
            float4 q0 = Qr[0], q1 = Qr[1], q2 = Qr[2];

            float2* o2 = (float2*)(out + (size_t)eidx * N_CLASS);
            o2[0] = make_float2(u[0] + p0.x + q0.x, u[1] + p0.y + q0.y);
            o2[1] = make_float2(u[2] + p0.z + q0.z, u[3] + p0.w + q0.w);
            o2[2] = make_float2(u[4] + p1.x + q1.x, u[5] + p1.y + q1.y);
            o2[3] = make_float2(u[6] + p1.z + q1.z, u[7] + p1.w + q1.w);
            o2[4] = make_float2(u[8] + p2.x + q2.x, u[9] + p2.y + q2.y);
        }
    }
}

// ---------------------------------------------------------------------------
extern "C" void kernel_launch(void* const* d_in, const int* in_sizes, int n_in,
                              void* d_out, int out_size) {
    const float* h   = (const float*)d_in[0];
    const float* eh  = (const float*)d_in[1];
    const float* W   = (const float*)d_in[2];
    const float* b   = (const float*)d_in[3];
    const int*   src = (const int*)d_in[4];
    const int*   dst = (const int*)d_in[5];
    float*       out = (float*)d_out;

    int n_nodes = in_sizes[0] / 128;
    int n_edges = in_sizes[4];

    proj_kernel<<<592, 128>>>(h, W, b, 0, n_nodes);   // g_P = h@W1^T + b
    proj_kernel<<<592, 128>>>(h, W, b, 1, n_nodes);   // g_Q = h@W2^T
    edge_score_kernel<<<1184, 128>>>(eh, W, src, dst, out, n_edges);
}

// round 10
// speedup vs baseline: 2.4412x; 1.2461x over previous
#include <cuda_runtime.h>

#define N_CLASS   10
#define PSTRIDE   12
#define MAX_NODES 100000

__device__ __align__(16) float g_P[MAX_NODES * PSTRIDE];
__device__ __align__(16) float g_Q[MAX_NODES * PSTRIDE];

// packed fp32x2 fma: acc += a * b
#define FFMA2(acc, a, b) \
    asm("fma.rn.f32x2 %0, %1, %2, %0;" : "+l"(acc) : "l"(a), "l"(b))

__device__ __forceinline__ unsigned long long pack2(float x, float y) {
    unsigned long long r;
    asm("mov.b64 %0, {%1, %2};" : "=l"(r) : "f"(x), "f"(y));
    return r;
}
__device__ __forceinline__ float2 unpack2(unsigned long long p) {
    float2 f;
    asm("mov.b64 {%0, %1}, %2;" : "=f"(f.x), "=f"(f.y) : "l"(p));
    return f;
}

// lane-resident weights: wp[p][k] = (W[2p][col], W[2p+1][col]) for this lane's 4 cols
__device__ __forceinline__ void load_weights(const float* __restrict__ W, int wcol,
                                             int lane, unsigned long long wp[5][4]) {
#pragma unroll
    for (int p = 0; p < 5; p++) {
        float4 wa = ((const float4*)(W + (2 * p) * 384 + wcol))[lane];
        float4 wb = ((const float4*)(W + (2 * p + 1) * 384 + wcol))[lane];
        wp[p][0] = pack2(wa.x, wb.x);
        wp[p][1] = pack2(wa.y, wb.y);
        wp[p][2] = pack2(wa.z, wb.z);
        wp[p][3] = pack2(wa.w, wb.w);
    }
}

__device__ __forceinline__ void dot10(const unsigned long long wp[5][4], float4 v,
                                      unsigned long long acc[5]) {
    unsigned long long a0 = pack2(v.x, v.x);
    unsigned long long a1 = pack2(v.y, v.y);
    unsigned long long a2 = pack2(v.z, v.z);
    unsigned long long a3 = pack2(v.w, v.w);
#pragma unroll
    for (int p = 0; p < 5; p++) {
        FFMA2(acc[p], a0, wp[p][0]);
        FFMA2(acc[p], a1, wp[p][1]);
        FFMA2(acc[p], a2, wp[p][2]);
        FFMA2(acc[p], a3, wp[p][3]);
    }
}

// Reduce 4 rows x 10 classes across the warp. After this, every lane of
// octet o holds the full 10-class result of row perm[o], perm = {0,2,1,3}.
__device__ __forceinline__ void reduce4x10(unsigned long long acc[4][5],
                                           float u[N_CLASS], int lane) {
    float p[4][N_CLASS];
#pragma unroll
    for (int g = 0; g < 4; g++)
#pragma unroll
        for (int q = 0; q < 5; q++) {
            float2 f = unpack2(acc[g][q]);
            p[g][2 * q] = f.x;
            p[g][2 * q + 1] = f.y;
        }

    bool lo16 = (lane & 16) == 0;
    float t0[N_CLASS], t1[N_CLASS];
#pragma unroll
    for (int c = 0; c < N_CLASS; c++) {
        float b0 = lo16 ? p[0][c] : p[1][c];
        float s0 = lo16 ? p[1][c] : p[0][c];
        t0[c] = b0 + __shfl_xor_sync(0xffffffffu, s0, 16);
        float b1 = lo16 ? p[2][c] : p[3][c];
        float s1 = lo16 ? p[3][c] : p[2][c];
        t1[c] = b1 + __shfl_xor_sync(0xffffffffu, s1, 16);
    }
    bool lo8 = (lane & 8) == 0;
#pragma unroll
    for (int c = 0; c < N_CLASS; c++) {
        float bc = lo8 ? t0[c] : t1[c];
        float sc = lo8 ? t1[c] : t0[c];
        float v = bc + __shfl_xor_sync(0xffffffffu, sc, 8);
        v += __shfl_xor_sync(0xffffffffu, v, 4);
        v += __shfl_xor_sync(0xffffffffu, v, 2);
        v += __shfl_xor_sync(0xffffffffu, v, 1);
        u[c] = v;
    }
}

// ---------------------------------------------------------------------------
// Node projection: which==0: g_P = h @ W[:,0:128]^T + b
//                  which==1: g_Q = h @ W[:,128:256]^T
// Software-pipelined: next pass's row loads issued before current compute.
// ---------------------------------------------------------------------------
__global__ __launch_bounds__(128)
void proj_kernel(const float* __restrict__ X, const float* __restrict__ W,
                 const float* __restrict__ bias, int which, int n_rows) {
    float* outbuf = which ? g_Q : g_P;
    int wcol = which ? 128 : 0;

    int lane = threadIdx.x & 31;
    int warp = (blockIdx.x * blockDim.x + threadIdx.x) >> 5;
    int nwarps = (gridDim.x * blockDim.x) >> 5;
    int o = lane >> 3, j = lane & 7;
    int operm = ((o & 1) << 1) | (o >> 1);     // octet -> row perm {0,2,1,3}
    int stride = nwarps * 4;

    unsigned long long wp[5][4];
    load_weights(W, wcol, lane, wp);

    // per-lane bias slice (j<3 stores classes 4j..4j+3 / 8..9)
    float bb0 = 0.f, bb1 = 0.f, bb2 = 0.f, bb3 = 0.f;
    if (which == 0 && j < 3) {
        bb0 = __ldg(bias + j * 4);
        bb1 = __ldg(bias + j * 4 + 1);
        if (j < 2) { bb2 = __ldg(bias + j * 4 + 2); bb3 = __ldg(bias + j * 4 + 3); }
    }

    const float4* Xv = (const float4*)X;
    int nm1 = n_rows - 1;

    int base = warp * 4;
    if (base >= n_rows) return;

    float4 v0 = Xv[(size_t)base * 32 + lane];
    float4 v1 = Xv[(size_t)min(base + 1, nm1) * 32 + lane];
    float4 v2 = Xv[(size_t)min(base + 2, nm1) * 32 + lane];
    float4 v3 = Xv[(size_t)min(base + 3, nm1) * 32 + lane];

    while (true) {
        int nb = base + stride;
        float4 n0, n1, n2, n3;
        bool has_next = nb < n_rows;
        if (has_next) {
            n0 = Xv[(size_t)nb * 32 + lane];
            n1 = Xv[(size_t)min(nb + 1, nm1) * 32 + lane];
            n2 = Xv[(size_t)min(nb + 2, nm1) * 32 + lane];
            n3 = Xv[(size_t)min(nb + 3, nm1) * 32 + lane];
        }

        unsigned long long acc[4][5];
#pragma unroll
        for (int g = 0; g < 4; g++)
#pragma unroll
            for (int q = 0; q < 5; q++) acc[g][q] = 0ull;
        dot10(wp, v0, acc[0]);
        dot10(wp, v1, acc[1]);
        dot10(wp, v2, acc[2]);
        dot10(wp, v3, acc[3]);

        float u[N_CLASS];
        reduce4x10(acc, u, lane);

        int ridx = base + operm;
        if (ridx < n_rows && j < 3) {
            float4* O = (float4*)(outbuf + (size_t)ridx * PSTRIDE);
            if (j == 0)      O[0] = make_float4(u[0] + bb0, u[1] + bb1, u[2] + bb2, u[3] + bb3);
            else if (j == 1) O[1] = make_float4(u[4] + bb0, u[5] + bb1, u[6] + bb2, u[7] + bb3);
            else             O[2] = make_float4(u[8] + bb0, u[9] + bb1, 0.f, 0.f);
        }

        if (!has_next) break;
        base = nb;
        v0 = n0; v1 = n1; v2 = n2; v3 = n3;
    }
}

// ---------------------------------------------------------------------------
// Edge kernel: out[e] = eh[e] @ W[:,256:384]^T + P[src[e]] + Q[dst[e]]
// Software-pipelined; epilogue gathers/stores split across 3 lanes per octet.
// ---------------------------------------------------------------------------
__global__ __launch_bounds__(128)
void edge_score_kernel(const float* __restrict__ eh, const float* __restrict__ W,
                       const int* __restrict__ src, const int* __restrict__ dst,
                       float* __restrict__ out, int n_edges) {
    int lane = threadIdx.x & 31;
    int warp = (blockIdx.x * blockDim.x + threadIdx.x) >> 5;
    int nwarps = (gridDim.x * blockDim.x) >> 5;
    int o = lane >> 3, j = lane & 7;
    int operm = ((o & 1) << 1) | (o >> 1);     // octet -> edge perm {0,2,1,3}
    int stride = nwarps * 4;

    unsigned long long wp[5][4];
    load_weights(W, 256, lane, wp);

    const float4* Ev = (const float4*)eh;
    int nm1 = n_edges - 1;

    int base = warp * 4;
    if (base >= n_edges) return;

    float4 v0 = Ev[(size_t)base * 32 + lane];
    float4 v1 = Ev[(size_t)min(base + 1, nm1) * 32 + lane];
    float4 v2 = Ev[(size_t)min(base + 2, nm1) * 32 + lane];
    float4 v3 = Ev[(size_t)min(base + 3, nm1) * 32 + lane];
    int ce = min(base + operm, nm1);
    int s = src[ce], d = dst[ce];               // all octet lanes: broadcast load

    while (true) {
        int nb = base + stride;
        float4 n0, n1, n2, n3;
        int ns = 0, nd = 0;
        bool has_next = nb < n_edges;
        if (has_next) {
            n0 = Ev[(size_t)nb * 32 + lane];
            n1 = Ev[(size_t)min(nb + 1, nm1) * 32 + lane];
            n2 = Ev[(size_t)min(nb + 2, nm1) * 32 + lane];
            n3 = Ev[(size_t)min(nb + 3, nm1) * 32 + lane];
            int ne = min(nb + operm, nm1);
            ns = src[ne]; nd = dst[ne];
        }

        unsigned long long acc[4][5];
#pragma unroll
        for (int g = 0; g < 4; g++)
#pragma unroll
            for (int q = 0; q < 5; q++) acc[g][q] = 0ull;
        dot10(wp, v0, acc[0]);
        dot10(wp, v1, acc[1]);
        dot10(wp, v2, acc[2]);
        dot10(wp, v3, acc[3]);

        float u[N_CLASS];
        reduce4x10(acc, u, lane);

        int eidx = base + operm;
        if (eidx < n_edges && j < 3) {
            float4 p = ((const float4*)(g_P + (size_t)s * PSTRIDE))[j];
            float4 q = ((const float4*)(g_Q + (size_t)d * PSTRIDE))[j];
            float2* o2 = (float2*)(out + (size_t)eidx * N_CLASS);
            if (j == 0) {
                o2[0] = make_float2(u[0] + p.x + q.x, u[1] + p.y + q.y);
                o2[1] = make_float2(u[2] + p.z + q.z, u[3] + p.w + q.w);
            } else if (j == 1) {
                o2[2] = make_float2(u[4] + p.x + q.x, u[5] + p.y + q.y);
                o2[3] = make_float2(u[6] + p.z + q.z, u[7] + p.w + q.w);
            } else {
                o2[4] = make_float2(u[8] + p.x + q.x, u[9] + p.y + q.y);
            }
        }

        if (!has_next) break;
        base = nb;
        v0 = n0; v1 = n1; v2 = n2; v3 = n3;
        s = ns; d = nd;
    }
}

// ---------------------------------------------------------------------------
extern "C" void kernel_launch(void* const* d_in, const int* in_sizes, int n_in,
                              void* d_out, int out_size) {
    const float* h   = (const float*)d_in[0];
    const float* eh  = (const float*)d_in[1];
    const float* W   = (const float*)d_in[2];
    const float* b   = (const float*)d_in[3];
    const int*   src = (const int*)d_in[4];
    const int*   dst = (const int*)d_in[5];
    float*       out = (float*)d_out;

    int n_nodes = in_sizes[0] / 128;
    int n_edges = in_sizes[4];

    proj_kernel<<<592, 128>>>(h, W, b, 0, n_nodes);   // g_P = h@W1^T + b
    proj_kernel<<<592, 128>>>(h, W, b, 1, n_nodes);   // g_Q = h@W2^T
    edge_score_kernel<<<1184, 128>>>(eh, W, src, dst, out, n_edges);
}